// round 2
// baseline (speedup 1.0000x reference)
#include <cuda_runtime.h>

// Problem constants
#define DD   64
#define EE   130
#define HH   8
#define NTOK 32768                 // B*N = 8*4096
#define ROWF 1040                  // H*E
#define SEGF ((size_t)NTOK * ROWF) // floats per output tensor (q|k|v)

#define WARPS   8
#define THREADS (WARPS * 32)
#define BLOCKS  (NTOK / (WARPS * 32))   // 128

// per-warp shared floats: xp1(32jp*66) + xp2(32jp*66) + smid(32) + slast(32)
#define XP_STRIDE 66
#define WARP_SH   4288
// two weight buffers (double-buffered prefetch) + per-warp x staging
#define SMEM_FLOATS (8192 + WARPS * WARP_SH)   // 42496 floats = 169984 B

// Packed f32x2 FMA: d = a*b + c (lane-wise on two packed floats).
// sm_100+: PTX fma.rn.f32x2 -> FFMA2 (2x fp32 pipe throughput vs FFMA).
__device__ __forceinline__ unsigned long long ffma2(unsigned long long a,
                                                    unsigned long long b,
                                                    unsigned long long c) {
    unsigned long long d;
    asm("fma.rn.f32x2 %0, %1, %2, %3;" : "=l"(d) : "l"(a), "l"(b), "l"(c));
    return d;
}

__device__ __forceinline__ float hadd2(unsigned long long a) {
    float lo, hi;
    asm("mov.b64 {%0, %1}, %2;" : "=f"(lo), "=f"(hi) : "l"(a));
    return lo + hi;
}

__global__ __launch_bounds__(THREADS) void fused_qkv_kernel(
    const float* __restrict__ x,
    const float* __restrict__ Mq,
    const float* __restrict__ Bq,
    const float* __restrict__ Mk,
    const float* __restrict__ Bk,
    const float* __restrict__ Mv,
    float* __restrict__ out)
{
    extern __shared__ float smem[];
    const int tid  = threadIdx.x;
    const int warp = tid >> 5;
    const int lane = tid & 31;

    float* wsh   = smem + 8192 + warp * WARP_SH;
    float* xp1   = wsh;            // paired-transposed x[0:64):   [jp][tok*2 + half]
    float* xp2   = wsh + 2112;     // paired-transposed x[65:129)
    float* smid  = wsh + 4224;     // x[64]  per token
    float* slast = wsh + 4256;     // x[129] per token

    const int g   = blockIdx.x * WARPS + warp;          // 32-token group id
    const int tok = g * 32 + lane;                      // this lane's token

    // matvec schedule: mi 0..3 = M_k (x1), 4..11 = M_v (x1), 12..15 = M_q (x2)
    // weight source pointer for matrix mi:
    auto wsrc_of = [&](int mi) -> const float* {
        if (mi < 4)  return Mk + mi * 4096;
        if (mi < 12) return Mv + (mi - 4) * 4096;
        return Mq + (mi - 12) * 4096;
    };

    // ------------------------------------------------------------------
    // Prefetch weight matrix 0 into buffer 0 (registers now, STS below).
    // ------------------------------------------------------------------
    float4 wpre[4];
    {
        const float4* w4 = reinterpret_cast<const float4*>(wsrc_of(0));
        #pragma unroll
        for (int r = 0; r < 4; ++r) wpre[r] = __ldg(w4 + tid + r * THREADS);
    }

    // ------------------------------------------------------------------
    // Stage this warp's 32 tokens of x (contiguous 4160 floats) into
    // shared, transposed to token-minor and packed in (j, j+1) pairs so
    // the mainloop can read a packed f32x2 operand with one LDS.64.
    // ------------------------------------------------------------------
    {
        const float4* xg = reinterpret_cast<const float4*>(x + (size_t)g * 32 * EE);
        for (int it = 0; it < 33; ++it) {
            int fidx = lane + it * 32;                  // float4 index, 0..1039
            if (fidx < 1040) {
                float4 v = __ldg(xg + fidx);
                int li = fidx * 4;
                float vals[4] = {v.x, v.y, v.z, v.w};
                #pragma unroll
                for (int c = 0; c < 4; ++c) {
                    int l  = li + c;
                    int tk = l / EE;
                    int e  = l - tk * EE;
                    float val = vals[c];
                    if (e < 64) {
                        xp1[(e >> 1) * XP_STRIDE + tk * 2 + (e & 1)] = val;
                    } else if (e == 64) {
                        smid[tk] = val;
                    } else if (e < 129) {
                        int e2 = e - 65;
                        xp2[(e2 >> 1) * XP_STRIDE + tk * 2 + (e2 & 1)] = val;
                    } else {
                        slast[tk] = val;
                    }
                }
            }
        }
    }

    // store prefetched matrix 0 into weight buffer 0
    {
        float4* sw4 = reinterpret_cast<float4*>(smem);
        #pragma unroll
        for (int r = 0; r < 4; ++r) sw4[tid + r * THREADS] = wpre[r];
    }
    __syncwarp();

    // ------------------------------------------------------------------
    // Zero-fill + bias scalars for this lane's token (q, k, v rows).
    // Row bases are even -> float2 stores are 8B aligned. L2 merges the
    // scattered 8B writes into full sectors (every byte of every row is
    // written exactly once across the kernel).
    // ------------------------------------------------------------------
    {
        const float  s_m = smid[lane];
        const float  s_l = slast[lane];
        const size_t tb  = (size_t)tok * ROWF;
        const float2 z2  = make_float2(0.f, 0.f);
        #pragma unroll 1
        for (int h = 0; h < HH; ++h) {
            const float bqh = __ldg(Bq + h);
            const float bkh = __ldg(Bk + h);
            float* q = out + tb + h * EE;
            float* k = out + SEGF + tb + h * EE;
            float* v = out + 2 * SEGF + tb + h * EE;
            float2* q2 = (float2*)q;
            float2* k2 = (float2*)k;
            float2* v2 = (float2*)v;
            #pragma unroll
            for (int j = 0; j < 32; ++j) { q2[j] = z2; k2[j] = z2; v2[j] = z2; }  // e [0,64)
            q[64] = 0.f; k[64] = 0.f; v[64] = 0.f;
            v[129] = 0.f;
            if (h < 4) {
                q[129] = s_l * bqh;        // rest of q/k row [65,129) is matvec output
                k[129] = s_l * bkh;
            } else {
                q[65] = s_l * bqh;
                k[65] = s_m * bkh;
                #pragma unroll
                for (int j = 33; j < 65; ++j) { q2[j] = z2; k2[j] = z2; }          // e [66,130)
            }
        }
    }
    __syncthreads();   // weight buffer 0 + all warps' x staging visible

    // ------------------------------------------------------------------
    // 16 mat-vec groups, double-buffered weights: prefetch mi+1 via LDG
    // at the top of iteration mi (latency hidden under compute), STS
    // into the other buffer after compute, single barrier per iteration
    // (BAR.SYNC drains the pending STS).
    // Mainloop reads weights as warp-uniform LDS.128 (broadcast,
    // conflict-free) and accumulates in packed f32x2 registers.
    // ------------------------------------------------------------------
    for (int mi = 0; mi < 16; ++mi) {
        // issue next matrix's global loads early
        if (mi + 1 < 16) {
            const float4* w4 = reinterpret_cast<const float4*>(wsrc_of(mi + 1));
            #pragma unroll
            for (int r = 0; r < 4; ++r) wpre[r] = __ldg(w4 + tid + r * THREADS);
        }

        size_t obase; int h;
        if (mi < 4)       { obase = SEGF;     h = mi; }
        else if (mi < 12) { obase = 2 * SEGF; h = mi - 4; }
        else              { obase = 0;        h = mi - 12; }

        const float* sw  = smem + (mi & 1) * 4096;
        const float* xp  = (mi < 12) ? xp1 : xp2;
        const float* xpl = xp + lane * 2;
        float* dst = out + obase + (size_t)tok * ROWF + h * EE + 65;

        #pragma unroll
        for (int ihalf = 0; ihalf < 2; ++ihalf) {
            unsigned long long acc[32];
            #pragma unroll
            for (int ii = 0; ii < 32; ++ii) acc[ii] = 0ULL;

            for (int jp2 = 0; jp2 < 16; ++jp2) {
                // packed x pairs (j=4*jp2 .. 4*jp2+3) for this lane's token
                unsigned long long xa =
                    *reinterpret_cast<const unsigned long long*>(xpl + (2 * jp2)     * XP_STRIDE);
                unsigned long long xb =
                    *reinterpret_cast<const unsigned long long*>(xpl + (2 * jp2 + 1) * XP_STRIDE);
                const ulonglong2* wp =
                    reinterpret_cast<const ulonglong2*>(sw + ihalf * 32 * 64 + 4 * jp2);
                #pragma unroll
                for (int ii = 0; ii < 32; ++ii) {
                    ulonglong2 wv = wp[ii * 16];        // row stride 64 floats = 16 ulonglong2
                    acc[ii] = ffma2(wv.x, xa, acc[ii]); // (w[j],w[j+1]) * (x[j],x[j+1])
                    acc[ii] = ffma2(wv.y, xb, acc[ii]);
                }
            }
            #pragma unroll
            for (int ii = 0; ii < 32; ++ii)
                dst[ihalf * 32 + ii] = hadd2(acc[ii]);
        }

        // store prefetched matrix into the other buffer; barrier both
        // publishes it and protects it from this iteration's stragglers
        if (mi + 1 < 16) {
            float4* sw4 = reinterpret_cast<float4*>(smem + ((mi + 1) & 1) * 4096);
            #pragma unroll
            for (int r = 0; r < 4; ++r) sw4[tid + r * THREADS] = wpre[r];
            __syncthreads();
        }
    }
}

extern "C" void kernel_launch(void* const* d_in, const int* in_sizes, int n_in,
                              void* d_out, int out_size) {
    const float* x  = (const float*)d_in[0];
    const float* Mq = (const float*)d_in[1];
    const float* Bq = (const float*)d_in[2];
    const float* Mk = (const float*)d_in[3];
    const float* Bk = (const float*)d_in[4];
    const float* Mv = (const float*)d_in[5];
    float* out = (float*)d_out;

    const size_t smem = SMEM_FLOATS * sizeof(float);   // 169984 B
    cudaFuncSetAttribute(fused_qkv_kernel,
                         cudaFuncAttributeMaxDynamicSharedMemorySize, (int)smem);
    fused_qkv_kernel<<<BLOCKS, THREADS, smem>>>(x, Mq, Bq, Mk, Bk, Mv, out);
}

// round 3
// speedup vs baseline: 1.8229x; 1.8229x over previous
#include <cuda_runtime.h>

// Problem constants
#define EE   130
#define HH   8
#define NTOK 32768                  // B*N
#define ROWF 1040                   // H*E
#define SEGF ((size_t)NTOK * ROWF)  // floats per output tensor (q|k|v)

#define THREADS 256
#define M_TILE  64
#define BLOCKS  (NTOK / M_TILE)     // 512

// smem layout (floats), all strides padded to 66 for bank-conflict-free LDS
#define XST 66
#define SX1_OFF   0                         // 64 x 66
#define SX2_OFF   (SX1_OFF + 64 * XST)      // 64 x 66
#define SMID_OFF  (SX2_OFF + 64 * XST)      // 64
#define SLAST_OFF (SMID_OFF + 64)           // 64
#define W_OFF     (SLAST_OFF + 64)          // 2 x (64 x 66) double buffer
#define WBUF      (64 * XST)
#define SMEM_FLOATS (W_OFF + 2 * WBUF)      // 17024 floats = 68096 B

typedef unsigned long long ull;

// Packed f32x2 FMA: d = a*b + c lane-wise on two packed floats (sm_100+ FFMA2).
__device__ __forceinline__ ull ffma2(ull a, ull b, ull c) {
    ull d;
    asm("fma.rn.f32x2 %0, %1, %2, %3;" : "=l"(d) : "l"(a), "l"(b), "l"(c));
    return d;
}
__device__ __forceinline__ float hadd2(ull a) {
    float lo, hi;
    asm("mov.b64 {%0, %1}, %2;" : "=f"(lo), "=f"(hi) : "l"(a));
    return lo + hi;
}

__global__ __launch_bounds__(THREADS, 2) void fused_qkv_kernel(
    const float* __restrict__ x,
    const float* __restrict__ Mq,
    const float* __restrict__ Bq,
    const float* __restrict__ Mk,
    const float* __restrict__ Bk,
    const float* __restrict__ Mv,
    float* __restrict__ out)
{
    extern __shared__ float sm[];
    float* sx1   = sm + SX1_OFF;    // x[:, 0:64)   token-major, stride 66
    float* sx2   = sm + SX2_OFF;    // x[:, 65:129) remapped to 0..63
    float* smid  = sm + SMID_OFF;   // x[:, 64]
    float* slast = sm + SLAST_OFF;  // x[:, 129]

    const int tid = threadIdx.x;
    const int tx  = tid & 15;       // output group:  oi in {tx, tx+16, tx+32, tx+48}
    const int ty  = tid >> 4;       // token  group:  ti in {ty, ty+16, ty+32, ty+48}
    const int t0  = blockIdx.x * M_TILE;

    // matvec schedule: mi 0..3 = M_k (x1,seg1), 4..11 = M_v (x1,seg2), 12..15 = M_q (x2,seg0)
    auto wsrc_of = [&](int mi) -> const float* {
        if (mi < 4)  return Mk + mi * 4096;
        if (mi < 12) return Mv + (mi - 4) * 4096;
        return Mq + (mi - 12) * 4096;
    };

    // ---- prefetch weight matrix 0 into registers ----
    float4 wpre[4];
    {
        const float4* w4 = reinterpret_cast<const float4*>(wsrc_of(0));
        #pragma unroll
        for (int r = 0; r < 4; ++r) wpre[r] = __ldg(w4 + tid + r * THREADS);
    }

    // ---- stage this block's 64 tokens of x into split smem ----
    {
        const float* xg = x + (size_t)t0 * EE;          // contiguous 8320 floats
        for (int idx = tid; idx < 64 * EE; idx += THREADS) {
            int t = idx / EE;
            int e = idx - t * EE;
            float v = __ldg(xg + idx);
            if (e < 64)        sx1[t * XST + e] = v;
            else if (e == 64)  smid[t] = v;
            else if (e < 129)  sx2[t * XST + (e - 65)] = v;
            else               slast[t] = v;
        }
    }

    // ---- store prefetched matrix 0 into weight buffer 0 (stride 66) ----
    {
        float* ws = sm + W_OFF;
        #pragma unroll
        for (int r = 0; r < 4; ++r) {
            int l = (tid + r * THREADS) * 4;            // linear float idx in 64x64
            int row = l >> 6, col = l & 63;
            float* p = ws + row * XST + col;            // col%4==0 -> 8B aligned
            *(float2*)(p)     = make_float2(wpre[r].x, wpre[r].y);
            *(float2*)(p + 2) = make_float2(wpre[r].z, wpre[r].w);
        }
    }
    __syncthreads();

    // ---- zero-fill + bias scalars for the 64 tokens (24 rows each) ----
    {
        const float2 z2 = make_float2(0.f, 0.f);
        for (int idx = tid; idx < 64 * 24; idx += THREADS) {
            int t = idx / 24;
            int r = idx - t * 24;
            int seg = r >> 3, h = r & 7;
            float* p = out + (size_t)seg * SEGF + (size_t)(t0 + t) * ROWF + h * EE;
            float2* p2 = (float2*)p;                    // row base even -> aligned
            #pragma unroll
            for (int j = 0; j < 32; ++j) p2[j] = z2;    // cols [0,64)
            p[64] = 0.f;
            if (seg == 2) {
                p[129] = 0.f;                           // v: cols 65..128 are matvec
            } else {
                float b = (seg == 0) ? __ldg(Bq + h) : __ldg(Bk + h);
                if (h < 4) {
                    p[129] = slast[t] * b;              // cols 65..128 matvec
                } else {
                    p[65] = ((seg == 0) ? slast[t] : smid[t]) * b;
                    #pragma unroll
                    for (int j = 33; j < 65; ++j) p2[j] = z2;   // cols [66,130)
                }
            }
        }
    }

    // ---- 16 matvec tiles, double-buffered weights ----
    for (int mi = 0; mi < 16; ++mi) {
        if (mi + 1 < 16) {
            const float4* w4 = reinterpret_cast<const float4*>(wsrc_of(mi + 1));
            #pragma unroll
            for (int r = 0; r < 4; ++r) wpre[r] = __ldg(w4 + tid + r * THREADS);
        }

        const float* ws = sm + W_OFF + (mi & 1) * WBUF;
        const float* xs = (mi < 12) ? sx1 : sx2;

        ull acc[4][4];
        #pragma unroll
        for (int i = 0; i < 4; ++i)
            #pragma unroll
            for (int o = 0; o < 4; ++o) acc[i][o] = 0ULL;

        #pragma unroll 2
        for (int jp = 0; jp < 32; ++jp) {
            ull xv[4], wv[4];
            #pragma unroll
            for (int i = 0; i < 4; ++i)
                xv[i] = *(const ull*)(xs + (ty + 16 * i) * XST + 2 * jp);
            #pragma unroll
            for (int o = 0; o < 4; ++o)
                wv[o] = *(const ull*)(ws + (tx + 16 * o) * XST + 2 * jp);
            #pragma unroll
            for (int i = 0; i < 4; ++i)
                #pragma unroll
                for (int o = 0; o < 4; ++o)
                    acc[i][o] = ffma2(wv[o], xv[i], acc[i][o]);
        }

        // output placement for this matrix
        size_t obase; int h;
        if (mi < 4)       { obase = SEGF;     h = mi; }
        else if (mi < 12) { obase = 2 * SEGF; h = mi - 4; }
        else              { obase = 0;        h = mi - 12; }

        #pragma unroll
        for (int i = 0; i < 4; ++i) {
            float* dst = out + obase + (size_t)(t0 + ty + 16 * i) * ROWF + h * EE + 65;
            #pragma unroll
            for (int o = 0; o < 4; ++o)
                dst[tx + 16 * o] = hadd2(acc[i][o]);    // lanes tx=0..15 -> 16 consecutive floats
        }

        if (mi + 1 < 16) {
            float* wd = sm + W_OFF + ((mi + 1) & 1) * WBUF;
            #pragma unroll
            for (int r = 0; r < 4; ++r) {
                int l = (tid + r * THREADS) * 4;
                int row = l >> 6, col = l & 63;
                float* p = wd + row * XST + col;
                *(float2*)(p)     = make_float2(wpre[r].x, wpre[r].y);
                *(float2*)(p + 2) = make_float2(wpre[r].z, wpre[r].w);
            }
            __syncthreads();
        }
    }
}

extern "C" void kernel_launch(void* const* d_in, const int* in_sizes, int n_in,
                              void* d_out, int out_size) {
    const float* x  = (const float*)d_in[0];
    const float* Mq = (const float*)d_in[1];
    const float* Bq = (const float*)d_in[2];
    const float* Mk = (const float*)d_in[3];
    const float* Bk = (const float*)d_in[4];
    const float* Mv = (const float*)d_in[5];
    float* out = (float*)d_out;

    const size_t smem = SMEM_FLOATS * sizeof(float);    // 68096 B
    cudaFuncSetAttribute(fused_qkv_kernel,
                         cudaFuncAttributeMaxDynamicSharedMemorySize, (int)smem);
    fused_qkv_kernel<<<BLOCKS, THREADS, smem>>>(x, Mq, Bq, Mk, Bk, Mv, out);
}

// round 4
// speedup vs baseline: 2.6460x; 1.4515x over previous
#include <cuda_runtime.h>

// Problem constants
#define EE   130
#define HH   8
#define NTOK 32768                  // B*N
#define ROWF 1040                   // H*E
#define SEGF ((size_t)NTOK * ROWF)  // floats per output tensor (q|k|v)

#define THREADS 512
#define M_TILE  64
#define BLOCKS  (NTOK / M_TILE)     // 512

// smem layout (floats); stride 66 keeps LDS conflict-free (2-bank row shift)
#define XST 66
#define SX1_OFF   0                         // 64 x 66
#define SX2_OFF   (SX1_OFF + 64 * XST)      // 64 x 66
#define SMID_OFF  (SX2_OFF + 64 * XST)      // 64
#define SLAST_OFF (SMID_OFF + 64)           // 64
#define W_OFF     (SLAST_OFF + 64)          // 2 x (64 x 66) double buffer
#define WBUF      (64 * XST)
#define SMEM_FLOATS (W_OFF + 2 * WBUF)      // 17024 floats = 68096 B

typedef unsigned long long ull;

// Packed f32x2 FMA (sm_100+ FFMA2): d = a*b + c lane-wise on two packed floats.
__device__ __forceinline__ ull ffma2(ull a, ull b, ull c) {
    ull d;
    asm("fma.rn.f32x2 %0, %1, %2, %3;" : "=l"(d) : "l"(a), "l"(b), "l"(c));
    return d;
}
__device__ __forceinline__ float hadd2(ull a) {
    float lo, hi;
    asm("mov.b64 {%0, %1}, %2;" : "=f"(lo), "=f"(hi) : "l"(a));
    return lo + hi;
}

__global__ __launch_bounds__(THREADS, 2) void fused_qkv_kernel(
    const float* __restrict__ x,
    const float* __restrict__ Mq,
    const float* __restrict__ Bq,
    const float* __restrict__ Mk,
    const float* __restrict__ Bk,
    const float* __restrict__ Mv,
    float* __restrict__ out)
{
    extern __shared__ float sm[];
    float* sx1   = sm + SX1_OFF;    // x[:, 0:64)   token-major, stride 66
    float* sx2   = sm + SX2_OFF;    // x[:, 65:129) remapped to 0..63
    float* smid  = sm + SMID_OFF;   // x[:, 64]
    float* slast = sm + SLAST_OFF;  // x[:, 129]

    const int tid  = threadIdx.x;
    const int warp = tid >> 5;      // 0..15
    const int lane = tid & 31;
    const int tx   = tid & 15;      // output group: oi in {tx, tx+16, tx+32, tx+48}
    const int ty   = tid >> 4;      // token  group: ti in {ty, ty+32}
    const int t0   = blockIdx.x * M_TILE;

    // matvec schedule: mi 0..3 = M_k (x1,seg1), 4..11 = M_v (x1,seg2), 12..15 = M_q (x2,seg0)
    auto wsrc_of = [&](int mi) -> const float* {
        if (mi < 4)  return Mk + mi * 4096;
        if (mi < 12) return Mv + (mi - 4) * 4096;
        return Mq + (mi - 12) * 4096;
    };

    // ---- prefetch weight matrix 0 into registers (2 float4 per thread) ----
    float4 wpre[2];
    {
        const float4* w4 = reinterpret_cast<const float4*>(wsrc_of(0));
        #pragma unroll
        for (int r = 0; r < 2; ++r) wpre[r] = __ldg(w4 + tid + r * THREADS);
    }

    // ---- stage this block's 64 tokens of x into split smem ----
    {
        const float* xg = x + (size_t)t0 * EE;          // contiguous 8320 floats
        for (int idx = tid; idx < M_TILE * EE; idx += THREADS) {
            int t = idx / EE;
            int e = idx - t * EE;
            float v = __ldg(xg + idx);
            if (e < 64)        sx1[t * XST + e] = v;
            else if (e == 64)  smid[t] = v;
            else if (e < 129)  sx2[t * XST + (e - 65)] = v;
            else               slast[t] = v;
        }
    }

    // ---- store prefetched matrix 0 into weight buffer 0 (stride 66) ----
    {
        float* ws = sm + W_OFF;
        #pragma unroll
        for (int r = 0; r < 2; ++r) {
            int l = (tid + r * THREADS) * 4;            // linear float idx in 64x64
            int row = l >> 6, col = l & 63;
            float* p = ws + row * XST + col;            // col%4==0 -> 8B aligned
            *(float2*)(p)     = make_float2(wpre[r].x, wpre[r].y);
            *(float2*)(p + 2) = make_float2(wpre[r].z, wpre[r].w);
        }
    }
    __syncthreads();    // x staging + weight buffer 0 visible to all

    // ------------------------------------------------------------------
    // Zero-fill + biases, warp-per-row (coalesced 256B stores).
    // Row classes (per token t, seg s, head h):
    //   A (v any h; q/k h<4): zero [0,65), col129 = 0 (v) or bias (q/k)
    //                         [65,129) is written by the matvec below.
    //   B (q/k h>=4):         zero [0,130) except col65 = bias.
    // ------------------------------------------------------------------
    {
        const float2 z2 = make_float2(0.f, 0.f);
        for (int rid = warp; rid < M_TILE * 24; rid += 16) {
            int t   = rid / 24;
            int r   = rid - t * 24;
            int seg = r >> 3, h = r & 7;
            float* p = out + (size_t)seg * SEGF + (size_t)(t0 + t) * ROWF + h * EE;

            // cols [0,64): 32 lanes x float2, contiguous 256B
            *(float2*)(p + 2 * lane) = z2;

            if (seg == 2 || h < 4) {                    // class A
                if (lane == 0) p[64] = 0.f;
                if (lane == 1) {
                    float v129 = 0.f;
                    if (seg == 0)      v129 = slast[t] * __ldg(Bq + h);
                    else if (seg == 1) v129 = slast[t] * __ldg(Bk + h);
                    p[129] = v129;
                }
            } else {                                    // class B: q/k h>=4
                // cols [64,128) via float2; lane 0's pair is (0, bias@65)
                float2 v = z2;
                if (lane == 0) {
                    float b = (seg == 0) ? __ldg(Bq + h) : __ldg(Bk + h);
                    v.y = ((seg == 0) ? slast[t] : smid[t]) * b;
                }
                *(float2*)(p + 64 + 2 * lane) = v;
                if (lane == 0) *(float2*)(p + 128) = z2;    // cols 128,129
            }
        }
    }

    // ---- 16 matvec tiles, double-buffered weights ----
    for (int mi = 0; mi < 16; ++mi) {
        if (mi + 1 < 16) {
            const float4* w4 = reinterpret_cast<const float4*>(wsrc_of(mi + 1));
            #pragma unroll
            for (int r = 0; r < 2; ++r) wpre[r] = __ldg(w4 + tid + r * THREADS);
        }

        const float* ws = sm + W_OFF + (mi & 1) * WBUF;
        const float* xs = (mi < 12) ? sx1 : sx2;

        ull acc[2][4];
        #pragma unroll
        for (int i = 0; i < 2; ++i)
            #pragma unroll
            for (int o = 0; o < 4; ++o) acc[i][o] = 0ULL;

        #pragma unroll 4
        for (int jp = 0; jp < 32; ++jp) {
            ull xv[2], wv[4];
            #pragma unroll
            for (int i = 0; i < 2; ++i)                 // broadcast (2 addrs/warp)
                xv[i] = *(const ull*)(xs + (ty + 32 * i) * XST + 2 * jp);
            #pragma unroll
            for (int o = 0; o < 4; ++o)                 // 16-distinct, conflict-free
                wv[o] = *(const ull*)(ws + (tx + 16 * o) * XST + 2 * jp);
            #pragma unroll
            for (int i = 0; i < 2; ++i)
                #pragma unroll
                for (int o = 0; o < 4; ++o)
                    acc[i][o] = ffma2(wv[o], xv[i], acc[i][o]);
        }

        size_t obase; int h;
        if (mi < 4)       { obase = SEGF;     h = mi; }
        else if (mi < 12) { obase = 2 * SEGF; h = mi - 4; }
        else              { obase = 0;        h = mi - 12; }

        #pragma unroll
        for (int i = 0; i < 2; ++i) {
            float* dst = out + obase + (size_t)(t0 + ty + 32 * i) * ROWF + h * EE + 65;
            #pragma unroll
            for (int o = 0; o < 4; ++o)
                dst[tx + 16 * o] = hadd2(acc[i][o]);    // half-warp: 16 consecutive floats
        }

        if (mi + 1 < 16) {
            float* wd = sm + W_OFF + ((mi + 1) & 1) * WBUF;
            #pragma unroll
            for (int r = 0; r < 2; ++r) {
                int l = (tid + r * THREADS) * 4;
                int row = l >> 6, col = l & 63;
                float* p = wd + row * XST + col;
                *(float2*)(p)     = make_float2(wpre[r].x, wpre[r].y);
                *(float2*)(p + 2) = make_float2(wpre[r].z, wpre[r].w);
            }
            __syncthreads();    // publishes wbuf(mi+1), protects wbuf(mi) reuse
        }
    }
}

extern "C" void kernel_launch(void* const* d_in, const int* in_sizes, int n_in,
                              void* d_out, int out_size) {
    const float* x  = (const float*)d_in[0];
    const float* Mq = (const float*)d_in[1];
    const float* Bq = (const float*)d_in[2];
    const float* Mk = (const float*)d_in[3];
    const float* Bk = (const float*)d_in[4];
    const float* Mv = (const float*)d_in[5];
    float* out = (float*)d_out;

    const size_t smem = SMEM_FLOATS * sizeof(float);    // 68096 B
    cudaFuncSetAttribute(fused_qkv_kernel,
                         cudaFuncAttributeMaxDynamicSharedMemorySize, (int)smem);
    fused_qkv_kernel<<<BLOCKS, THREADS, smem>>>(x, Mq, Bq, Bk ? Mk : Mk, Bk, Mv, out);
}